// round 14
// baseline (speedup 1.0000x reference)
#include <cuda_runtime.h>
#include <cuda_fp16.h>
#include <cstdint>

constexpr int Bb = 4, Ss = 2048, Dd = 1024, Mtot = 8192;

// ---------------------------------------------------------------------------
// Tiled split-fp16 scratch. All GEMM operands live as contiguous 4KB blocks of
// [128 rows x 16 halves], pre-swizzled for conflict-free LDS fragment loads.
#define DG __device__ __align__(16)
DG __half t_Ehi[(size_t)Mtot * Dd];
DG __half t_Elo[(size_t)Mtot * Dd];
DG __half t_Whi[(size_t)3 * Dd * Dd];     // W^T tiled: [z][ntile 8][kchunk 64]
DG __half t_Wlo[(size_t)3 * Dd * Dd];
DG __half t_Qhi[(size_t)Mtot * Dd];       // [rowtile 64][chunk 64]
DG __half t_Qlo[(size_t)Mtot * Dd];
DG __half t_Khi[(size_t)Mtot * Dd];
DG __half t_Klo[(size_t)Mtot * Dd];
DG __half t_VThi[(size_t)Bb * Dd * Ss];   // [b][dtile 8][schunk 128]
DG __half t_VTlo[(size_t)Bb * Dd * Ss];
DG float  g_S[(size_t)Bb * Ss * Ss];      // fp32 scores, row-major
DG __half t_Phi[(size_t)Bb * Ss * Ss];    // [b][qtile 16][schunk 128]
DG __half t_Plo[(size_t)Bb * Ss * Ss];

// ---------------------------------------------------------------------------
// Swizzle: byte offset of b32 unit (row, c2) inside a 4KB block (rows of 32B).
__device__ __host__ __forceinline__ uint32_t swz(int row, int c2) {
    return (uint32_t)(row * 32 + ((c2 ^ (row & 4)) << 2));
}

__device__ __forceinline__ uint32_t smem_u32(const void* p) {
    uint32_t a;
    asm("{ .reg .u64 t; cvta.to.shared.u64 t, %1; cvt.u32.u64 %0, t; }" : "=r"(a) : "l"(p));
    return a;
}
__device__ __forceinline__ void cp16(uint32_t s, const void* g) {
    asm volatile("cp.async.cg.shared.global [%0], [%1], 16;\n" :: "r"(s), "l"(g));
}
#define CP_COMMIT() asm volatile("cp.async.commit_group;\n" ::: "memory")
#define CP_WAIT2()  asm volatile("cp.async.wait_group 2;\n" ::: "memory")
#define CP_WAIT0()  asm volatile("cp.async.wait_group 0;\n" ::: "memory")

__device__ __forceinline__ uint32_t packh(__half a, __half b) {
    __half2 t = __halves2half2(a, b);
    return *reinterpret_cast<uint32_t*>(&t);
}
__device__ __forceinline__ void split2(float v0, float v1, uint32_t& hi, uint32_t& lo) {
    __half h0 = __float2half(v0), h1 = __float2half(v1);
    __half l0 = __float2half(v0 - __half2float(h0));
    __half l1 = __float2half(v1 - __half2float(h1));
    hi = packh(h0, h1);
    lo = packh(l0, l1);
}

// ---------------------------------------------------------------------------
// GEMM core: 128x128 CTA tile, K-chunks of 32 (two k-steps of 16 per stage),
// 3-stage cp.async.cg pipeline. Stage layout (32KB):
//   Ahi: [0, 8K)   (kstep0 @ +0, kstep1 @ +4096)
//   Alo: [8K,16K)  Bhi: [16K,24K)  Blo: [24K,32K)
// 8 warps, warp tile 64x32.
constexpr int STAGE = 32768;
constexpr int SMEM_TOTAL = 3 * STAGE;   // 96KB -> needs MaxDynamicSharedMemorySize opt-in

__device__ __forceinline__ void mma16816(float* d, const uint32_t* a, uint32_t b0, uint32_t b1) {
    asm volatile("mma.sync.aligned.m16n8k16.row.col.f32.f16.f16.f32 "
        "{%0,%1,%2,%3}, {%4,%5,%6,%7}, {%8,%9}, {%0,%1,%2,%3};"
        : "+f"(d[0]), "+f"(d[1]), "+f"(d[2]), "+f"(d[3])
        : "r"(a[0]), "r"(a[1]), "r"(a[2]), "r"(a[3]), "r"(b0), "r"(b1));
}

// Each thread copies 2x16B from each of the 4 operand streams (chunk = 8KB/op).
__device__ __forceinline__ void issue_chunk(uint32_t sb, int s,
        const char* Ahi, const char* Alo, const char* Bhi, const char* Blo,
        int c, int tid) {
    size_t off = (size_t)c * 8192 + tid * 16;
    uint32_t d = sb + s * STAGE + tid * 16;
    cp16(d,          Ahi + off);
    cp16(d + 4096,   Ahi + off + 4096);
    cp16(d + 8192,   Alo + off);
    cp16(d + 12288,  Alo + off + 4096);
    cp16(d + 16384,  Bhi + off);
    cp16(d + 20480,  Bhi + off + 4096);
    cp16(d + 24576,  Blo + off);
    cp16(d + 28672,  Blo + off + 4096);
}

// One K=16 k-step; reg-lean pass order (ah,bh) -> +al -> +bl.
__device__ __forceinline__ void compute_kstep(const char* st, int lane, int wr, int wc,
                                              float acc[4][4][4]) {
    const int c2 = lane & 3, rr = lane >> 2;
    uint32_t ah[4][4], bh[4][2];
#pragma unroll
    for (int ni = 0; ni < 4; ni++) {
        int n = wc * 32 + ni * 8 + rr;
        bh[ni][0] = *(const uint32_t*)(st + 16384 + swz(n, c2));
        bh[ni][1] = *(const uint32_t*)(st + 16384 + swz(n, c2 + 4));
    }
#pragma unroll
    for (int mi = 0; mi < 4; mi++) {
        int r = wr * 64 + mi * 16 + rr;
        ah[mi][0] = *(const uint32_t*)(st + swz(r, c2));
        ah[mi][1] = *(const uint32_t*)(st + swz(r + 8, c2));
        ah[mi][2] = *(const uint32_t*)(st + swz(r, c2 + 4));
        ah[mi][3] = *(const uint32_t*)(st + swz(r + 8, c2 + 4));
    }
#pragma unroll
    for (int mi = 0; mi < 4; mi++)
#pragma unroll
        for (int ni = 0; ni < 4; ni++)
            mma16816(acc[mi][ni], ah[mi], bh[ni][0], bh[ni][1]);

    {
        uint32_t al[4][4];
#pragma unroll
        for (int mi = 0; mi < 4; mi++) {
            int r = wr * 64 + mi * 16 + rr;
            al[mi][0] = *(const uint32_t*)(st + 8192 + swz(r, c2));
            al[mi][1] = *(const uint32_t*)(st + 8192 + swz(r + 8, c2));
            al[mi][2] = *(const uint32_t*)(st + 8192 + swz(r, c2 + 4));
            al[mi][3] = *(const uint32_t*)(st + 8192 + swz(r + 8, c2 + 4));
        }
#pragma unroll
        for (int mi = 0; mi < 4; mi++)
#pragma unroll
            for (int ni = 0; ni < 4; ni++)
                mma16816(acc[mi][ni], al[mi], bh[ni][0], bh[ni][1]);
    }
    {
        uint32_t bl[4][2];
#pragma unroll
        for (int ni = 0; ni < 4; ni++) {
            int n = wc * 32 + ni * 8 + rr;
            bl[ni][0] = *(const uint32_t*)(st + 24576 + swz(n, c2));
            bl[ni][1] = *(const uint32_t*)(st + 24576 + swz(n, c2 + 4));
        }
#pragma unroll
        for (int mi = 0; mi < 4; mi++)
#pragma unroll
            for (int ni = 0; ni < 4; ni++)
                mma16816(acc[mi][ni], ah[mi], bl[ni][0], bl[ni][1]);
    }
}

// 3-stage pipeline, always-commit so wait_group<2> retires exactly chunk c.
// nc counts K=32 chunks.
__device__ void gemm_run(const __half* Ahi_, const __half* Alo_,
                         const __half* Bhi_, const __half* Blo_,
                         int nc, float acc[4][4][4]) {
    extern __shared__ char dsm[];
    const char* Ahi = (const char*)Ahi_;
    const char* Alo = (const char*)Alo_;
    const char* Bhi = (const char*)Bhi_;
    const char* Blo = (const char*)Blo_;
    const int tid = threadIdx.x, lane = tid & 31, wid = tid >> 5;
    const int wr = wid >> 2, wc = wid & 3;
    const uint32_t sb = smem_u32(dsm);

    // Prologue: 3 committed groups (possibly empty beyond nc).
#pragma unroll
    for (int i = 0; i < 3; i++) {
        if (i < nc) issue_chunk(sb, i, Ahi, Alo, Bhi, Blo, i, tid);
        CP_COMMIT();
    }
    for (int c = 0; c < nc; c++) {
        const int s = c % 3;
        CP_WAIT2();                 // all but 2 newest groups done => chunk c done
        __syncthreads();            // make every thread's copies visible
        const char* st = dsm + s * STAGE;
        compute_kstep(st, lane, wr, wc, acc);
        compute_kstep(st + 4096, lane, wr, wc, acc);
        __syncthreads();            // stage s fully consumed before refill
        if (c + 3 < nc) issue_chunk(sb, s, Ahi, Alo, Bhi, Blo, c + 3, tid);
        CP_COMMIT();                // always commit: uniform group accounting
    }
    CP_WAIT0();
}

// ---------------------------------------------------------------------------
// Pre-passes
__global__ __launch_bounds__(256) void convert_e(const float* __restrict__ E) {
    const int ch = blockIdx.x, rt = blockIdx.y;
    const int t = threadIdx.x, row = t >> 1, g = t & 1;
    const float* src = E + (size_t)(rt * 128 + row) * Dd + ch * 16 + g * 8;
    float4 v0 = *(const float4*)src, v1 = *(const float4*)(src + 4);
    float vs[8] = {v0.x, v0.y, v0.z, v0.w, v1.x, v1.y, v1.z, v1.w};
    char* bh = (char*)t_Ehi + ((size_t)rt * 64 + ch) * 4096;
    char* bl = (char*)t_Elo + ((size_t)rt * 64 + ch) * 4096;
#pragma unroll
    for (int j = 0; j < 4; j++) {
        uint32_t hi, lo;
        split2(vs[2 * j], vs[2 * j + 1], hi, lo);
        int c2 = g * 4 + j;
        *(uint32_t*)(bh + swz(row, c2)) = hi;
        *(uint32_t*)(bl + swz(row, c2)) = lo;
    }
}

__global__ __launch_bounds__(256) void convert_w(const float* __restrict__ W0,
                                                 const float* __restrict__ W1,
                                                 const float* __restrict__ W2) {
    __shared__ float sm[16][132];
    const int nt = blockIdx.x, kc = blockIdx.y, z = blockIdx.z;
    const float* W = (z == 0) ? W0 : (z == 1) ? W1 : W2;
    const int t = threadIdx.x;
    {
        int kk = t >> 4, seg = t & 15;
        const float* s = W + (size_t)(kc * 16 + kk) * Dd + nt * 128 + seg * 8;
        float4 a = *(const float4*)s, b = *(const float4*)(s + 4);
        sm[kk][seg * 8 + 0] = a.x; sm[kk][seg * 8 + 1] = a.y;
        sm[kk][seg * 8 + 2] = a.z; sm[kk][seg * 8 + 3] = a.w;
        sm[kk][seg * 8 + 4] = b.x; sm[kk][seg * 8 + 5] = b.y;
        sm[kk][seg * 8 + 6] = b.z; sm[kk][seg * 8 + 7] = b.w;
    }
    __syncthreads();
    const int n = t >> 1, g = t & 1;
    char* bh = (char*)t_Whi + ((size_t)(z * 8 + nt) * 64 + kc) * 4096;
    char* bl = (char*)t_Wlo + ((size_t)(z * 8 + nt) * 64 + kc) * 4096;
#pragma unroll
    for (int j = 0; j < 4; j++) {
        int c2 = g * 4 + j;
        uint32_t hi, lo;
        split2(sm[2 * c2][n], sm[2 * c2 + 1][n], hi, lo);
        *(uint32_t*)(bh + swz(n, c2)) = hi;
        *(uint32_t*)(bl + swz(n, c2)) = lo;
    }
}

// ---------------------------------------------------------------------------
// GEMM kernels (occupancy 2)
// qkv: z<2 writes Q/K tiled blocks; z==2 stages the tile in smem and writes
// V directly in TRANSPOSED VT-block layout (transpose_v kernel eliminated).
__global__ __launch_bounds__(256, 2) void qkv_mma() {
    extern __shared__ char dsm[];
    const int nt = blockIdx.x, rt = blockIdx.y, z = blockIdx.z;
    float acc[4][4][4] = {};
    const size_t astride = (size_t)64 * 2048;
    gemm_run(t_Ehi + (size_t)rt * astride, t_Elo + (size_t)rt * astride,
             t_Whi + (size_t)(z * 8 + nt) * astride, t_Wlo + (size_t)(z * 8 + nt) * astride,
             32, acc);

    const int tid = threadIdx.x, lane = tid & 31, wid = tid >> 5;
    const int wr = wid >> 2, wc = wid & 3;

    if (z < 2) {
        __half* Hi = (z == 0) ? t_Qhi : t_Khi;
        __half* Lo = (z == 0) ? t_Qlo : t_Klo;
#pragma unroll
        for (int mi = 0; mi < 4; mi++)
#pragma unroll
            for (int ni = 0; ni < 4; ni++)
#pragma unroll
                for (int h = 0; h < 2; h++) {
                    uint32_t hi, lo;
                    split2(acc[mi][ni][h * 2], acc[mi][ni][h * 2 + 1], hi, lo);
                    int R = wr * 64 + mi * 16 + (lane >> 2) + h * 8;
                    int chunk = nt * 8 + wc * 2 + (ni >> 1);
                    int c2 = (ni & 1) * 4 + (lane & 3);
                    size_t blk = ((size_t)rt * 64 + chunk) * 4096;
                    *(uint32_t*)((char*)Hi + blk + swz(R, c2)) = hi;
                    *(uint32_t*)((char*)Lo + blk + swz(R, c2)) = lo;
                }
    } else {
        // Stage tile (hi/lo halves) into smem: row-major [128][136].
        __syncthreads();            // all warps done reading stages
        __half* sh = (__half*)dsm;
        __half* sl = sh + 128 * 136;
#pragma unroll
        for (int mi = 0; mi < 4; mi++)
#pragma unroll
            for (int ni = 0; ni < 4; ni++)
#pragma unroll
                for (int h = 0; h < 2; h++) {
                    uint32_t hi, lo;
                    split2(acc[mi][ni][h * 2], acc[mi][ni][h * 2 + 1], hi, lo);
                    int r = wr * 64 + mi * 16 + (lane >> 2) + h * 8;
                    int c0 = wc * 32 + ni * 8 + (lane & 3) * 2;
                    *(uint32_t*)(sh + r * 136 + c0) = hi;
                    *(uint32_t*)(sl + r * 136 + c0) = lo;
                }
        __syncthreads();
        // Transposed write: s global = rt*128 + r, d global = nt*128 + c.
        // VT block = ((b*8 + nt)*128 + sc); word (d_local=c, c2) packs s pair.
        const int b = rt >> 4;
        const int sc_base = (rt & 15) * 8;
        char* oh0 = (char*)t_VThi + ((size_t)(b * 8 + nt) * 128 + sc_base) * 4096;
        char* ol0 = (char*)t_VTlo + ((size_t)(b * 8 + nt) * 128 + sc_base) * 4096;
#pragma unroll
        for (int i = 0; i < 32; i++) {
            int idx = i * 256 + tid;          // 0..8191
            int d = idx & 127;                // d_local (block row)
            int w = idx >> 7;                 // 0..63
            int sc_local = w >> 3;            // 0..7
            int c2 = w & 7;                   // 0..7
            int r = sc_local * 16 + c2 * 2;   // s-local pair base
            uint32_t off = (size_t)sc_local * 4096 + swz(d, c2);
            *(uint32_t*)(oh0 + off) = packh(sh[r * 136 + d], sh[(r + 1) * 136 + d]);
            *(uint32_t*)(ol0 + off) = packh(sl[r * 136 + d], sl[(r + 1) * 136 + d]);
        }
    }
}

// Packed lower-triangle grid: blockIdx.x in [0,136) -> (qt, kt), blockIdx.y = b.
__global__ __launch_bounds__(256, 2) void scores_mma() {
    int idx = blockIdx.x;
    int qt = (int)((sqrtf(8.0f * idx + 1.0f) - 1.0f) * 0.5f);
    while ((qt + 1) * (qt + 2) / 2 <= idx) qt++;
    while (qt * (qt + 1) / 2 > idx) qt--;
    const int kt = idx - qt * (qt + 1) / 2;
    const int b = blockIdx.y;

    float acc[4][4][4] = {};
    const size_t astride = (size_t)64 * 2048;
    gemm_run(t_Qhi + (size_t)(b * 16 + qt) * astride, t_Qlo + (size_t)(b * 16 + qt) * astride,
             t_Khi + (size_t)(b * 16 + kt) * astride, t_Klo + (size_t)(b * 16 + kt) * astride,
             32, acc);

    float* out = g_S + (size_t)b * Ss * Ss;
    const int tid = threadIdx.x, lane = tid & 31, wid = tid >> 5;
    const int wr = wid >> 2, wc = wid & 3;
#pragma unroll
    for (int mi = 0; mi < 4; mi++)
#pragma unroll
        for (int ni = 0; ni < 4; ni++)
#pragma unroll
            for (int h = 0; h < 2; h++) {
                int R = qt * 128 + wr * 64 + mi * 16 + (lane >> 2) + h * 8;
                int C = kt * 128 + wc * 32 + ni * 8 + (lane & 3) * 2;
                float2 v = make_float2(acc[mi][ni][h * 2] * 0.03125f,
                                       acc[mi][ni][h * 2 + 1] * 0.03125f);
                *(float2*)(out + (size_t)R * Ss + C) = v;
            }
}

__global__ __launch_bounds__(256) void softmax_kernel() {
    __shared__ float sbuf[Ss];
    __shared__ float red[8];
    const int q = blockIdx.x, b = blockIdx.y;
    const float* row = g_S + ((size_t)b * Ss + q) * Ss;
    const int len = q + 1, tid = threadIdx.x;

    float m = -3.4e38f;
    for (int k = tid; k < len; k += 256) {
        float v = row[k];
        sbuf[k] = v;
        m = fmaxf(m, v);
    }
#pragma unroll
    for (int o = 16; o; o >>= 1) m = fmaxf(m, __shfl_xor_sync(0xffffffffu, m, o));
    if ((tid & 31) == 0) red[tid >> 5] = m;
    __syncthreads();
    float mall = red[0];
#pragma unroll
    for (int i = 1; i < 8; i++) mall = fmaxf(mall, red[i]);
    __syncthreads();

    float s = 0.f;
    for (int k = tid; k < len; k += 256) {
        float e = __expf(sbuf[k] - mall);
        sbuf[k] = e;
        s += e;
    }
#pragma unroll
    for (int o = 16; o; o >>= 1) s += __shfl_xor_sync(0xffffffffu, s, o);
    if ((tid & 31) == 0) red[tid >> 5] = s;
    __syncthreads();
    float sall = 0.f;
#pragma unroll
    for (int i = 0; i < 8; i++) sall += red[i];
    const float inv = 1.0f / sall;
    // (the sync above also makes all sbuf exp writes visible)

    const int fe = ((q >> 7) + 1) << 7;       // zero-fill through the PV k-tile
    char* Ph = (char*)t_Phi + ((size_t)(b * 16 + (q >> 7)) * 128) * 4096;
    char* Pl = (char*)t_Plo + ((size_t)(b * 16 + (q >> 7)) * 128) * 4096;
    const int qr = q & 127;
    for (int k = 2 * tid; k < fe; k += 512) {
        float p0 = (k     < len) ? sbuf[k] * inv : 0.f;
        float p1 = (k + 1 < len) ? sbuf[k + 1] * inv : 0.f;
        uint32_t hi, lo;
        split2(p0, p1, hi, lo);
        size_t blk = (size_t)(k >> 4) * 4096;
        int c2 = (k & 15) >> 1;
        *(uint32_t*)(Ph + blk + swz(qr, c2)) = hi;
        *(uint32_t*)(Pl + blk + swz(qr, c2)) = lo;
    }
}

// Longest q-tiles scheduled first: qt = 15 - blockIdx.x.
__global__ __launch_bounds__(256, 2) void pv_mma(float* __restrict__ O) {
    const int qt = 15 - blockIdx.x, dt = blockIdx.y, b = blockIdx.z;
    float acc[4][4][4] = {};
    const size_t pstride = (size_t)128 * 2048;
    gemm_run(t_Phi + (size_t)(b * 16 + qt) * pstride, t_Plo + (size_t)(b * 16 + qt) * pstride,
             t_VThi + (size_t)(b * 8 + dt) * pstride, t_VTlo + (size_t)(b * 8 + dt) * pstride,
             (qt + 1) * 4, acc);

    float* out = O + (size_t)b * Ss * Dd;
    const int tid = threadIdx.x, lane = tid & 31, wid = tid >> 5;
    const int wr = wid >> 2, wc = wid & 3;
#pragma unroll
    for (int mi = 0; mi < 4; mi++)
#pragma unroll
        for (int ni = 0; ni < 4; ni++)
#pragma unroll
            for (int h = 0; h < 2; h++) {
                int R = qt * 128 + wr * 64 + mi * 16 + (lane >> 2) + h * 8;
                int C = dt * 128 + wc * 32 + ni * 8 + (lane & 3) * 2;
                float2 v = make_float2(acc[mi][ni][h * 2], acc[mi][ni][h * 2 + 1]);
                *(float2*)(out + (size_t)R * Dd + C) = v;
            }
}

// ---------------------------------------------------------------------------
extern "C" void kernel_launch(void* const* d_in, const int* in_sizes, int n_in,
                              void* d_out, int out_size) {
    const float* E  = (const float*)d_in[0];
    const float* WQ = (const float*)d_in[1];
    const float* WK = (const float*)d_in[2];
    const float* WV = (const float*)d_in[3];
    float* O = (float*)d_out;

    // 96KB dynamic smem opt-in (legal under capture; executes immediately).
    cudaFuncSetAttribute(qkv_mma,    cudaFuncAttributeMaxDynamicSharedMemorySize, SMEM_TOTAL);
    cudaFuncSetAttribute(scores_mma, cudaFuncAttributeMaxDynamicSharedMemorySize, SMEM_TOTAL);
    cudaFuncSetAttribute(pv_mma,     cudaFuncAttributeMaxDynamicSharedMemorySize, SMEM_TOTAL);

    convert_e<<<dim3(64, 64), 256>>>(E);
    convert_w<<<dim3(8, 64, 3), 256>>>(WQ, WK, WV);
    qkv_mma<<<dim3(8, 64, 3), 256, SMEM_TOTAL>>>();
    scores_mma<<<dim3(136, 4), 256, SMEM_TOTAL>>>();
    softmax_kernel<<<dim3(2048, 4), 256>>>();
    pv_mma<<<dim3(16, 8, 4), 256, SMEM_TOTAL>>>(O);
}

// round 15
// speedup vs baseline: 1.0194x; 1.0194x over previous
#include <cuda_runtime.h>
#include <cuda_fp16.h>
#include <cstdint>

constexpr int Bb = 4, Ss = 2048, Dd = 1024, Mtot = 8192;

// ---------------------------------------------------------------------------
// Tiled split-fp16 scratch. All GEMM operands live as contiguous 4KB blocks of
// [128 rows x 16 halves], pre-swizzled for conflict-free LDS fragment loads.
#define DG __device__ __align__(16)
DG __half t_Ehi[(size_t)Mtot * Dd];
DG __half t_Elo[(size_t)Mtot * Dd];
DG __half t_Whi[(size_t)3 * Dd * Dd];     // W^T tiled: [z][ntile 8][kchunk 64]
DG __half t_Wlo[(size_t)3 * Dd * Dd];
DG __half t_Qhi[(size_t)Mtot * Dd];       // [rowtile 64][chunk 64]
DG __half t_Qlo[(size_t)Mtot * Dd];
DG __half t_Khi[(size_t)Mtot * Dd];
DG __half t_Klo[(size_t)Mtot * Dd];
DG __half t_Vhi[(size_t)Mtot * Dd];
DG __half t_Vlo[(size_t)Mtot * Dd];
DG __half t_VThi[(size_t)Bb * Dd * Ss];   // [b][dtile 8][schunk 128]
DG __half t_VTlo[(size_t)Bb * Dd * Ss];
DG float  g_S[(size_t)Bb * Ss * Ss];      // fp32 scores, row-major
DG __half t_Phi[(size_t)Bb * Ss * Ss];    // [b][qtile 16][schunk 128]
DG __half t_Plo[(size_t)Bb * Ss * Ss];

// ---------------------------------------------------------------------------
// Swizzle: byte offset of b32 unit (row, c2) inside a 4KB block (rows of 32B).
__device__ __host__ __forceinline__ uint32_t swz(int row, int c2) {
    return (uint32_t)(row * 32 + ((c2 ^ (row & 4)) << 2));
}

__device__ __forceinline__ uint32_t smem_u32(const void* p) {
    uint32_t a;
    asm("{ .reg .u64 t; cvta.to.shared.u64 t, %1; cvt.u32.u64 %0, t; }" : "=r"(a) : "l"(p));
    return a;
}
__device__ __forceinline__ void cp16(uint32_t s, const void* g) {
    asm volatile("cp.async.cg.shared.global [%0], [%1], 16;\n" :: "r"(s), "l"(g));
}
#define CP_COMMIT() asm volatile("cp.async.commit_group;\n" ::: "memory")
#define CP_WAIT1()  asm volatile("cp.async.wait_group 1;\n" ::: "memory")

__device__ __forceinline__ uint32_t packh(__half a, __half b) {
    __half2 t = __halves2half2(a, b);
    return *reinterpret_cast<uint32_t*>(&t);
}
__device__ __forceinline__ void split2(float v0, float v1, uint32_t& hi, uint32_t& lo) {
    __half h0 = __float2half(v0), h1 = __float2half(v1);
    __half l0 = __float2half(v0 - __half2float(h0));
    __half l1 = __float2half(v1 - __half2float(h1));
    hi = packh(h0, h1);
    lo = packh(l0, l1);
}

// ---------------------------------------------------------------------------
// GEMM core: 128x128 CTA tile, K-chunks of 32 (two k-steps of 16 per stage),
// 3-stage cp.async.cg pipeline, ONE barrier per chunk. Stage layout (32KB):
//   Ahi: [0, 8K)   (kstep0 @ +0, kstep1 @ +4096)
//   Alo: [8K,16K)  Bhi: [16K,24K)  Blo: [24K,32K)
// 8 warps, warp tile 64x32.
constexpr int STAGE = 32768;
constexpr int SMEM_TOTAL = 3 * STAGE;   // 96KB -> needs MaxDynamicSharedMemorySize opt-in

__device__ __forceinline__ void mma16816(float* d, const uint32_t* a, uint32_t b0, uint32_t b1) {
    asm volatile("mma.sync.aligned.m16n8k16.row.col.f32.f16.f16.f32 "
        "{%0,%1,%2,%3}, {%4,%5,%6,%7}, {%8,%9}, {%0,%1,%2,%3};"
        : "+f"(d[0]), "+f"(d[1]), "+f"(d[2]), "+f"(d[3])
        : "r"(a[0]), "r"(a[1]), "r"(a[2]), "r"(a[3]), "r"(b0), "r"(b1));
}

// Each thread copies 2x16B from each of the 4 operand streams (chunk = 8KB/op).
__device__ __forceinline__ void issue_chunk(uint32_t sb, int s,
        const char* Ahi, const char* Alo, const char* Bhi, const char* Blo,
        int c, int tid) {
    size_t off = (size_t)c * 8192 + tid * 16;
    uint32_t d = sb + s * STAGE + tid * 16;
    cp16(d,          Ahi + off);
    cp16(d + 4096,   Ahi + off + 4096);
    cp16(d + 8192,   Alo + off);
    cp16(d + 12288,  Alo + off + 4096);
    cp16(d + 16384,  Bhi + off);
    cp16(d + 20480,  Bhi + off + 4096);
    cp16(d + 24576,  Blo + off);
    cp16(d + 28672,  Blo + off + 4096);
}

// One K=16 k-step; reg-lean pass order (ah,bh) -> +al -> +bl.
__device__ __forceinline__ void compute_kstep(const char* st, int lane, int wr, int wc,
                                              float acc[4][4][4]) {
    const int c2 = lane & 3, rr = lane >> 2;
    uint32_t ah[4][4], bh[4][2];
#pragma unroll
    for (int ni = 0; ni < 4; ni++) {
        int n = wc * 32 + ni * 8 + rr;
        bh[ni][0] = *(const uint32_t*)(st + 16384 + swz(n, c2));
        bh[ni][1] = *(const uint32_t*)(st + 16384 + swz(n, c2 + 4));
    }
#pragma unroll
    for (int mi = 0; mi < 4; mi++) {
        int r = wr * 64 + mi * 16 + rr;
        ah[mi][0] = *(const uint32_t*)(st + swz(r, c2));
        ah[mi][1] = *(const uint32_t*)(st + swz(r + 8, c2));
        ah[mi][2] = *(const uint32_t*)(st + swz(r, c2 + 4));
        ah[mi][3] = *(const uint32_t*)(st + swz(r + 8, c2 + 4));
    }
#pragma unroll
    for (int mi = 0; mi < 4; mi++)
#pragma unroll
        for (int ni = 0; ni < 4; ni++)
            mma16816(acc[mi][ni], ah[mi], bh[ni][0], bh[ni][1]);

    {
        uint32_t al[4][4];
#pragma unroll
        for (int mi = 0; mi < 4; mi++) {
            int r = wr * 64 + mi * 16 + rr;
            al[mi][0] = *(const uint32_t*)(st + 8192 + swz(r, c2));
            al[mi][1] = *(const uint32_t*)(st + 8192 + swz(r + 8, c2));
            al[mi][2] = *(const uint32_t*)(st + 8192 + swz(r, c2 + 4));
            al[mi][3] = *(const uint32_t*)(st + 8192 + swz(r + 8, c2 + 4));
        }
#pragma unroll
        for (int mi = 0; mi < 4; mi++)
#pragma unroll
            for (int ni = 0; ni < 4; ni++)
                mma16816(acc[mi][ni], al[mi], bh[ni][0], bh[ni][1]);
    }
    {
        uint32_t bl[4][2];
#pragma unroll
        for (int ni = 0; ni < 4; ni++) {
            int n = wc * 32 + ni * 8 + rr;
            bl[ni][0] = *(const uint32_t*)(st + 24576 + swz(n, c2));
            bl[ni][1] = *(const uint32_t*)(st + 24576 + swz(n, c2 + 4));
        }
#pragma unroll
        for (int mi = 0; mi < 4; mi++)
#pragma unroll
            for (int ni = 0; ni < 4; ni++)
                mma16816(acc[mi][ni], ah[mi], bl[ni][0], bl[ni][1]);
    }
}

// 3-stage pipeline, ONE barrier per chunk. Prologue commits chunks 0,1.
// Iter c: wait1 (=> chunk c resident), barrier (=> chunk c-1 in stage
// (c+2)%3 fully consumed by ALL threads), refill that stage with chunk c+2
// (copies fly during compute), then compute chunk c. Always-commit keeps
// group accounting uniform. nc counts K=32 chunks.
__device__ void gemm_run(const __half* Ahi_, const __half* Alo_,
                         const __half* Bhi_, const __half* Blo_,
                         int nc, float acc[4][4][4]) {
    extern __shared__ char dsm[];
    const char* Ahi = (const char*)Ahi_;
    const char* Alo = (const char*)Alo_;
    const char* Bhi = (const char*)Bhi_;
    const char* Blo = (const char*)Blo_;
    const int tid = threadIdx.x, lane = tid & 31, wid = tid >> 5;
    const int wr = wid >> 2, wc = wid & 3;
    const uint32_t sb = smem_u32(dsm);

    issue_chunk(sb, 0, Ahi, Alo, Bhi, Blo, 0, tid);
    CP_COMMIT();
    if (nc > 1) issue_chunk(sb, 1, Ahi, Alo, Bhi, Blo, 1, tid);
    CP_COMMIT();

    for (int c = 0; c < nc; c++) {
        const int s = c % 3;
        CP_WAIT1();                 // groups <= c complete => chunk c resident
        __syncthreads();            // visibility + stage (c+2)%3 fully consumed
        if (c + 2 < nc) issue_chunk(sb, (c + 2) % 3, Ahi, Alo, Bhi, Blo, c + 2, tid);
        CP_COMMIT();
        const char* st = dsm + s * STAGE;
        compute_kstep(st, lane, wr, wc, acc);
        compute_kstep(st + 4096, lane, wr, wc, acc);
    }
}

// ---------------------------------------------------------------------------
// Pre-passes
__global__ __launch_bounds__(256) void convert_e(const float* __restrict__ E) {
    const int ch = blockIdx.x, rt = blockIdx.y;
    const int t = threadIdx.x, row = t >> 1, g = t & 1;
    const float* src = E + (size_t)(rt * 128 + row) * Dd + ch * 16 + g * 8;
    float4 v0 = *(const float4*)src, v1 = *(const float4*)(src + 4);
    float vs[8] = {v0.x, v0.y, v0.z, v0.w, v1.x, v1.y, v1.z, v1.w};
    char* bh = (char*)t_Ehi + ((size_t)rt * 64 + ch) * 4096;
    char* bl = (char*)t_Elo + ((size_t)rt * 64 + ch) * 4096;
#pragma unroll
    for (int j = 0; j < 4; j++) {
        uint32_t hi, lo;
        split2(vs[2 * j], vs[2 * j + 1], hi, lo);
        int c2 = g * 4 + j;
        *(uint32_t*)(bh + swz(row, c2)) = hi;
        *(uint32_t*)(bl + swz(row, c2)) = lo;
    }
}

__global__ __launch_bounds__(256) void convert_w(const float* __restrict__ W0,
                                                 const float* __restrict__ W1,
                                                 const float* __restrict__ W2) {
    __shared__ float sm[16][132];
    const int nt = blockIdx.x, kc = blockIdx.y, z = blockIdx.z;
    const float* W = (z == 0) ? W0 : (z == 1) ? W1 : W2;
    const int t = threadIdx.x;
    {
        int kk = t >> 4, seg = t & 15;
        const float* s = W + (size_t)(kc * 16 + kk) * Dd + nt * 128 + seg * 8;
        float4 a = *(const float4*)s, b = *(const float4*)(s + 4);
        sm[kk][seg * 8 + 0] = a.x; sm[kk][seg * 8 + 1] = a.y;
        sm[kk][seg * 8 + 2] = a.z; sm[kk][seg * 8 + 3] = a.w;
        sm[kk][seg * 8 + 4] = b.x; sm[kk][seg * 8 + 5] = b.y;
        sm[kk][seg * 8 + 6] = b.z; sm[kk][seg * 8 + 7] = b.w;
    }
    __syncthreads();
    const int n = t >> 1, g = t & 1;
    char* bh = (char*)t_Whi + ((size_t)(z * 8 + nt) * 64 + kc) * 4096;
    char* bl = (char*)t_Wlo + ((size_t)(z * 8 + nt) * 64 + kc) * 4096;
#pragma unroll
    for (int j = 0; j < 4; j++) {
        int c2 = g * 4 + j;
        uint32_t hi, lo;
        split2(sm[2 * c2][n], sm[2 * c2 + 1][n], hi, lo);
        *(uint32_t*)(bh + swz(n, c2)) = hi;
        *(uint32_t*)(bl + swz(n, c2)) = lo;
    }
}

__global__ __launch_bounds__(256) void transpose_v() {
    __shared__ __half th[16][136];
    __shared__ __half tl[16][136];
    const int sc = blockIdx.x, dt = blockIdx.y, b = blockIdx.z;
    const int t = threadIdx.x;
    const int srt = sc >> 3, srow0 = (sc & 7) * 16;
#pragma unroll
    for (int i = 0; i < 4; i++) {
        int idx = i * 256 + t;
        int dc = idx >> 7, rr = (idx >> 3) & 15, c2 = idx & 7;
        const char* vh = (const char*)t_Vhi + ((size_t)(b * 16 + srt) * 64 + dt * 8 + dc) * 4096;
        const char* vl = (const char*)t_Vlo + ((size_t)(b * 16 + srt) * 64 + dt * 8 + dc) * 4096;
        uint32_t uh = *(const uint32_t*)(vh + swz(srow0 + rr, c2));
        uint32_t ul = *(const uint32_t*)(vl + swz(srow0 + rr, c2));
        __half2 hh = *(__half2*)&uh, hl = *(__half2*)&ul;
        int d = dc * 16 + c2 * 2;
        th[rr][d] = __low2half(hh); th[rr][d + 1] = __high2half(hh);
        tl[rr][d] = __low2half(hl); tl[rr][d + 1] = __high2half(hl);
    }
    __syncthreads();
    char* oh = (char*)t_VThi + ((size_t)(b * 8 + dt) * 128 + sc) * 4096;
    char* ol = (char*)t_VTlo + ((size_t)(b * 8 + dt) * 128 + sc) * 4096;
#pragma unroll
    for (int i = 0; i < 4; i++) {
        int idx = i * 256 + t;
        int d = idx >> 3, c2 = idx & 7;
        *(uint32_t*)(oh + swz(d, c2)) = packh(th[2 * c2][d], th[2 * c2 + 1][d]);
        *(uint32_t*)(ol + swz(d, c2)) = packh(tl[2 * c2][d], tl[2 * c2 + 1][d]);
    }
}

// ---------------------------------------------------------------------------
// GEMM kernels (occupancy 2)
__global__ __launch_bounds__(256, 2) void qkv_mma() {
    const int nt = blockIdx.x, rt = blockIdx.y, z = blockIdx.z;
    float acc[4][4][4] = {};
    const size_t astride = (size_t)64 * 2048;
    gemm_run(t_Ehi + (size_t)rt * astride, t_Elo + (size_t)rt * astride,
             t_Whi + (size_t)(z * 8 + nt) * astride, t_Wlo + (size_t)(z * 8 + nt) * astride,
             32, acc);

    __half* Hi = (z == 0) ? t_Qhi : (z == 1) ? t_Khi : t_Vhi;
    __half* Lo = (z == 0) ? t_Qlo : (z == 1) ? t_Klo : t_Vlo;
    const int tid = threadIdx.x, lane = tid & 31, wid = tid >> 5;
    const int wr = wid >> 2, wc = wid & 3;
#pragma unroll
    for (int mi = 0; mi < 4; mi++)
#pragma unroll
        for (int ni = 0; ni < 4; ni++)
#pragma unroll
            for (int h = 0; h < 2; h++) {
                uint32_t hi, lo;
                split2(acc[mi][ni][h * 2], acc[mi][ni][h * 2 + 1], hi, lo);
                int R = wr * 64 + mi * 16 + (lane >> 2) + h * 8;
                int chunk = nt * 8 + wc * 2 + (ni >> 1);
                int c2 = (ni & 1) * 4 + (lane & 3);
                size_t blk = ((size_t)rt * 64 + chunk) * 4096;
                *(uint32_t*)((char*)Hi + blk + swz(R, c2)) = hi;
                *(uint32_t*)((char*)Lo + blk + swz(R, c2)) = lo;
            }
}

__global__ __launch_bounds__(256, 2) void scores_mma() {
    const int kt = blockIdx.x, qt = blockIdx.y, b = blockIdx.z;
    if (kt > qt) return;
    float acc[4][4][4] = {};
    const size_t astride = (size_t)64 * 2048;
    gemm_run(t_Qhi + (size_t)(b * 16 + qt) * astride, t_Qlo + (size_t)(b * 16 + qt) * astride,
             t_Khi + (size_t)(b * 16 + kt) * astride, t_Klo + (size_t)(b * 16 + kt) * astride,
             32, acc);

    float* out = g_S + (size_t)b * Ss * Ss;
    const int tid = threadIdx.x, lane = tid & 31, wid = tid >> 5;
    const int wr = wid >> 2, wc = wid & 3;
#pragma unroll
    for (int mi = 0; mi < 4; mi++)
#pragma unroll
        for (int ni = 0; ni < 4; ni++)
#pragma unroll
            for (int h = 0; h < 2; h++) {
                int R = qt * 128 + wr * 64 + mi * 16 + (lane >> 2) + h * 8;
                int C = kt * 128 + wc * 32 + ni * 8 + (lane & 3) * 2;
                float2 v = make_float2(acc[mi][ni][h * 2] * 0.03125f,
                                       acc[mi][ni][h * 2 + 1] * 0.03125f);
                *(float2*)(out + (size_t)R * Ss + C) = v;
            }
}

__global__ __launch_bounds__(256) void softmax_kernel() {
    __shared__ float sbuf[Ss];
    __shared__ float red[8];
    const int q = blockIdx.x, b = blockIdx.y;
    const float* row = g_S + ((size_t)b * Ss + q) * Ss;
    const int len = q + 1, tid = threadIdx.x;

    float m = -3.4e38f;
    for (int k = tid; k < len; k += 256) {
        float v = row[k];
        sbuf[k] = v;
        m = fmaxf(m, v);
    }
#pragma unroll
    for (int o = 16; o; o >>= 1) m = fmaxf(m, __shfl_xor_sync(0xffffffffu, m, o));
    if ((tid & 31) == 0) red[tid >> 5] = m;
    __syncthreads();
    float mall = red[0];
#pragma unroll
    for (int i = 1; i < 8; i++) mall = fmaxf(mall, red[i]);
    __syncthreads();

    float s = 0.f;
    for (int k = tid; k < len; k += 256) {
        float e = __expf(sbuf[k] - mall);
        sbuf[k] = e;
        s += e;
    }
#pragma unroll
    for (int o = 16; o; o >>= 1) s += __shfl_xor_sync(0xffffffffu, s, o);
    if ((tid & 31) == 0) red[tid >> 5] = s;
    __syncthreads();
    float sall = 0.f;
#pragma unroll
    for (int i = 0; i < 8; i++) sall += red[i];
    const float inv = 1.0f / sall;
    // (the sync above also makes all sbuf exp writes visible)

    const int fe = ((q >> 7) + 1) << 7;       // zero-fill through the PV k-tile
    char* Ph = (char*)t_Phi + ((size_t)(b * 16 + (q >> 7)) * 128) * 4096;
    char* Pl = (char*)t_Plo + ((size_t)(b * 16 + (q >> 7)) * 128) * 4096;
    const int qr = q & 127;
    for (int k = 2 * tid; k < fe; k += 512) {
        float p0 = (k     < len) ? sbuf[k] * inv : 0.f;
        float p1 = (k + 1 < len) ? sbuf[k + 1] * inv : 0.f;
        uint32_t hi, lo;
        split2(p0, p1, hi, lo);
        size_t blk = (size_t)(k >> 4) * 4096;
        int c2 = (k & 15) >> 1;
        *(uint32_t*)(Ph + blk + swz(qr, c2)) = hi;
        *(uint32_t*)(Pl + blk + swz(qr, c2)) = lo;
    }
}

// Longest q-tiles scheduled first: qt = 15 - blockIdx.x.
__global__ __launch_bounds__(256, 2) void pv_mma(float* __restrict__ O) {
    const int qt = 15 - blockIdx.x, dt = blockIdx.y, b = blockIdx.z;
    float acc[4][4][4] = {};
    const size_t pstride = (size_t)128 * 2048;
    gemm_run(t_Phi + (size_t)(b * 16 + qt) * pstride, t_Plo + (size_t)(b * 16 + qt) * pstride,
             t_VThi + (size_t)(b * 8 + dt) * pstride, t_VTlo + (size_t)(b * 8 + dt) * pstride,
             (qt + 1) * 4, acc);

    float* out = O + (size_t)b * Ss * Dd;
    const int tid = threadIdx.x, lane = tid & 31, wid = tid >> 5;
    const int wr = wid >> 2, wc = wid & 3;
#pragma unroll
    for (int mi = 0; mi < 4; mi++)
#pragma unroll
        for (int ni = 0; ni < 4; ni++)
#pragma unroll
            for (int h = 0; h < 2; h++) {
                int R = qt * 128 + wr * 64 + mi * 16 + (lane >> 2) + h * 8;
                int C = dt * 128 + wc * 32 + ni * 8 + (lane & 3) * 2;
                float2 v = make_float2(acc[mi][ni][h * 2], acc[mi][ni][h * 2 + 1]);
                *(float2*)(out + (size_t)R * Dd + C) = v;
            }
}

// ---------------------------------------------------------------------------
extern "C" void kernel_launch(void* const* d_in, const int* in_sizes, int n_in,
                              void* d_out, int out_size) {
    const float* E  = (const float*)d_in[0];
    const float* WQ = (const float*)d_in[1];
    const float* WK = (const float*)d_in[2];
    const float* WV = (const float*)d_in[3];
    float* O = (float*)d_out;

    // 96KB dynamic smem opt-in (legal under capture; executes immediately).
    cudaFuncSetAttribute(qkv_mma,    cudaFuncAttributeMaxDynamicSharedMemorySize, SMEM_TOTAL);
    cudaFuncSetAttribute(scores_mma, cudaFuncAttributeMaxDynamicSharedMemorySize, SMEM_TOTAL);
    cudaFuncSetAttribute(pv_mma,     cudaFuncAttributeMaxDynamicSharedMemorySize, SMEM_TOTAL);

    convert_e<<<dim3(64, 64), 256>>>(E);
    convert_w<<<dim3(8, 64, 3), 256>>>(WQ, WK, WV);
    qkv_mma<<<dim3(8, 64, 3), 256, SMEM_TOTAL>>>();
    transpose_v<<<dim3(128, 8, 4), 256>>>();
    scores_mma<<<dim3(16, 16, 4), 256, SMEM_TOTAL>>>();
    softmax_kernel<<<dim3(2048, 4), 256>>>();
    pv_mma<<<dim3(16, 8, 4), 256, SMEM_TOTAL>>>(O);
}

// round 17
// speedup vs baseline: 1.0321x; 1.0125x over previous
#include <cuda_runtime.h>
#include <cuda_fp16.h>
#include <cstdint>

constexpr int Bb = 4, Ss = 2048, Dd = 1024, Mtot = 8192;

// ---------------------------------------------------------------------------
// Tiled split-fp16 scratch. All GEMM operands live as contiguous 4KB blocks of
// [128 rows x 16 halves], pre-swizzled for conflict-free LDS fragment loads.
#define DG __device__ __align__(16)
DG __half t_Ehi[(size_t)Mtot * Dd];
DG __half t_Elo[(size_t)Mtot * Dd];
DG __half t_Whi[(size_t)3 * Dd * Dd];     // W^T tiled: [z][ntile 8][kchunk 64]
DG __half t_Wlo[(size_t)3 * Dd * Dd];
DG __half t_Qhi[(size_t)Mtot * Dd];       // [rowtile 64][chunk 64]
DG __half t_Qlo[(size_t)Mtot * Dd];
DG __half t_Khi[(size_t)Mtot * Dd];
DG __half t_Klo[(size_t)Mtot * Dd];
DG __half t_Vhi[(size_t)Mtot * Dd];
DG __half t_Vlo[(size_t)Mtot * Dd];
DG __half t_VThi[(size_t)Bb * Dd * Ss];   // [b][dtile 8][schunk 128]
DG __half t_VTlo[(size_t)Bb * Dd * Ss];
DG float  g_S[(size_t)Bb * Ss * Ss];      // fp32 scores, row-major
DG __half t_Phi[(size_t)Bb * Ss * Ss];    // [b][qtile 16][schunk 128]
DG __half t_Plo[(size_t)Bb * Ss * Ss];

// ---------------------------------------------------------------------------
// Swizzle: byte offset of b32 unit (row, c2) inside a 4KB block (rows of 32B).
__device__ __host__ __forceinline__ uint32_t swz(int row, int c2) {
    return (uint32_t)(row * 32 + ((c2 ^ (row & 4)) << 2));
}

__device__ __forceinline__ uint32_t smem_u32(const void* p) {
    uint32_t a;
    asm("{ .reg .u64 t; cvta.to.shared.u64 t, %1; cvt.u32.u64 %0, t; }" : "=r"(a) : "l"(p));
    return a;
}
__device__ __forceinline__ void cp16(uint32_t s, const void* g) {
    asm volatile("cp.async.cg.shared.global [%0], [%1], 16;\n" :: "r"(s), "l"(g));
}
#define CP_COMMIT() asm volatile("cp.async.commit_group;\n" ::: "memory")
#define CP_WAIT1()  asm volatile("cp.async.wait_group 1;\n" ::: "memory")

__device__ __forceinline__ uint32_t packh(__half a, __half b) {
    __half2 t = __halves2half2(a, b);
    return *reinterpret_cast<uint32_t*>(&t);
}
__device__ __forceinline__ void split2(float v0, float v1, uint32_t& hi, uint32_t& lo) {
    __half h0 = __float2half(v0), h1 = __float2half(v1);
    __half l0 = __float2half(v0 - __half2float(h0));
    __half l1 = __float2half(v1 - __half2float(h1));
    hi = packh(h0, h1);
    lo = packh(l0, l1);
}

// ---------------------------------------------------------------------------
// GEMM core: 128x128 CTA tile, K-chunks of 32 (two k-steps of 16 per stage),
// 3-stage cp.async.cg pipeline, ONE barrier per chunk. Stage layout (32KB):
//   Ahi: [0, 8K)   (kstep0 @ +0, kstep1 @ +4096)
//   Alo: [8K,16K)  Bhi: [16K,24K)  Blo: [24K,32K)
// 8 warps, warp tile 64x32.
constexpr int STAGE = 32768;
constexpr int SMEM_TOTAL = 3 * STAGE;   // 96KB -> needs MaxDynamicSharedMemorySize opt-in

__device__ __forceinline__ void mma16816(float* d, const uint32_t* a, uint32_t b0, uint32_t b1) {
    asm volatile("mma.sync.aligned.m16n8k16.row.col.f32.f16.f16.f32 "
        "{%0,%1,%2,%3}, {%4,%5,%6,%7}, {%8,%9}, {%0,%1,%2,%3};"
        : "+f"(d[0]), "+f"(d[1]), "+f"(d[2]), "+f"(d[3])
        : "r"(a[0]), "r"(a[1]), "r"(a[2]), "r"(a[3]), "r"(b0), "r"(b1));
}

// Each thread copies 2x16B from each of the 4 operand streams (chunk = 8KB/op).
__device__ __forceinline__ void issue_chunk(uint32_t sb, int s,
        const char* Ahi, const char* Alo, const char* Bhi, const char* Blo,
        int c, int tid) {
    size_t off = (size_t)c * 8192 + tid * 16;
    uint32_t d = sb + s * STAGE + tid * 16;
    cp16(d,          Ahi + off);
    cp16(d + 4096,   Ahi + off + 4096);
    cp16(d + 8192,   Alo + off);
    cp16(d + 12288,  Alo + off + 4096);
    cp16(d + 16384,  Bhi + off);
    cp16(d + 20480,  Bhi + off + 4096);
    cp16(d + 24576,  Blo + off);
    cp16(d + 28672,  Blo + off + 4096);
}

// One K=16 k-step; reg-lean pass order (ah,bh) -> +al -> +bl.
__device__ __forceinline__ void compute_kstep(const char* st, int lane, int wr, int wc,
                                              float acc[4][4][4]) {
    const int c2 = lane & 3, rr = lane >> 2;
    uint32_t ah[4][4], bh[4][2];
#pragma unroll
    for (int ni = 0; ni < 4; ni++) {
        int n = wc * 32 + ni * 8 + rr;
        bh[ni][0] = *(const uint32_t*)(st + 16384 + swz(n, c2));
        bh[ni][1] = *(const uint32_t*)(st + 16384 + swz(n, c2 + 4));
    }
#pragma unroll
    for (int mi = 0; mi < 4; mi++) {
        int r = wr * 64 + mi * 16 + rr;
        ah[mi][0] = *(const uint32_t*)(st + swz(r, c2));
        ah[mi][1] = *(const uint32_t*)(st + swz(r + 8, c2));
        ah[mi][2] = *(const uint32_t*)(st + swz(r, c2 + 4));
        ah[mi][3] = *(const uint32_t*)(st + swz(r + 8, c2 + 4));
    }
#pragma unroll
    for (int mi = 0; mi < 4; mi++)
#pragma unroll
        for (int ni = 0; ni < 4; ni++)
            mma16816(acc[mi][ni], ah[mi], bh[ni][0], bh[ni][1]);

    {
        uint32_t al[4][4];
#pragma unroll
        for (int mi = 0; mi < 4; mi++) {
            int r = wr * 64 + mi * 16 + rr;
            al[mi][0] = *(const uint32_t*)(st + 8192 + swz(r, c2));
            al[mi][1] = *(const uint32_t*)(st + 8192 + swz(r + 8, c2));
            al[mi][2] = *(const uint32_t*)(st + 8192 + swz(r, c2 + 4));
            al[mi][3] = *(const uint32_t*)(st + 8192 + swz(r + 8, c2 + 4));
        }
#pragma unroll
        for (int mi = 0; mi < 4; mi++)
#pragma unroll
            for (int ni = 0; ni < 4; ni++)
                mma16816(acc[mi][ni], al[mi], bh[ni][0], bh[ni][1]);
    }
    {
        uint32_t bl[4][2];
#pragma unroll
        for (int ni = 0; ni < 4; ni++) {
            int n = wc * 32 + ni * 8 + rr;
            bl[ni][0] = *(const uint32_t*)(st + 24576 + swz(n, c2));
            bl[ni][1] = *(const uint32_t*)(st + 24576 + swz(n, c2 + 4));
        }
#pragma unroll
        for (int mi = 0; mi < 4; mi++)
#pragma unroll
            for (int ni = 0; ni < 4; ni++)
                mma16816(acc[mi][ni], ah[mi], bl[ni][0], bl[ni][1]);
    }
}

// 3-stage pipeline, ONE barrier per chunk. Prologue commits chunks 0,1.
// Iter c: wait1 (=> chunk c resident), barrier (=> chunk c-1 in stage
// (c+2)%3 fully consumed by ALL threads), refill that stage with chunk c+2
// (copies fly during compute), then compute chunk c. Always-commit keeps
// group accounting uniform. nc counts K=32 chunks.
__device__ void gemm_run(const __half* Ahi_, const __half* Alo_,
                         const __half* Bhi_, const __half* Blo_,
                         int nc, float acc[4][4][4]) {
    extern __shared__ char dsm[];
    const char* Ahi = (const char*)Ahi_;
    const char* Alo = (const char*)Alo_;
    const char* Bhi = (const char*)Bhi_;
    const char* Blo = (const char*)Blo_;
    const int tid = threadIdx.x, lane = tid & 31, wid = tid >> 5;
    const int wr = wid >> 2, wc = wid & 3;
    const uint32_t sb = smem_u32(dsm);

    issue_chunk(sb, 0, Ahi, Alo, Bhi, Blo, 0, tid);
    CP_COMMIT();
    if (nc > 1) issue_chunk(sb, 1, Ahi, Alo, Bhi, Blo, 1, tid);
    CP_COMMIT();

    for (int c = 0; c < nc; c++) {
        const int s = c % 3;
        CP_WAIT1();                 // groups <= c complete => chunk c resident
        __syncthreads();            // visibility + stage (c+2)%3 fully consumed
        if (c + 2 < nc) issue_chunk(sb, (c + 2) % 3, Ahi, Alo, Bhi, Blo, c + 2, tid);
        CP_COMMIT();
        const char* st = dsm + s * STAGE;
        compute_kstep(st, lane, wr, wc, acc);
        compute_kstep(st + 4096, lane, wr, wc, acc);
    }
}

// ---------------------------------------------------------------------------
// Pre-pass: fused convert (E blocks + W blocks in one grid).
// x < 64: convert_e(ch=x, rt=y).  x >= 64: convert_w(nt=(x-64)&7, z=(x-64)>>3, kc=y).
__global__ __launch_bounds__(256) void convert_ew(const float* __restrict__ E,
                                                  const float* __restrict__ W0,
                                                  const float* __restrict__ W1,
                                                  const float* __restrict__ W2) {
    const int t = threadIdx.x;
    if (blockIdx.x < 64) {
        const int ch = blockIdx.x, rt = blockIdx.y;
        const int row = t >> 1, g = t & 1;
        const float* src = E + (size_t)(rt * 128 + row) * Dd + ch * 16 + g * 8;
        float4 v0 = *(const float4*)src, v1 = *(const float4*)(src + 4);
        float vs[8] = {v0.x, v0.y, v0.z, v0.w, v1.x, v1.y, v1.z, v1.w};
        char* bh = (char*)t_Ehi + ((size_t)rt * 64 + ch) * 4096;
        char* bl = (char*)t_Elo + ((size_t)rt * 64 + ch) * 4096;
#pragma unroll
        for (int j = 0; j < 4; j++) {
            uint32_t hi, lo;
            split2(vs[2 * j], vs[2 * j + 1], hi, lo);
            int c2 = g * 4 + j;
            *(uint32_t*)(bh + swz(row, c2)) = hi;
            *(uint32_t*)(bl + swz(row, c2)) = lo;
        }
    } else {
        __shared__ float sm[16][132];
        const int xw = blockIdx.x - 64;
        const int nt = xw & 7, z = xw >> 3, kc = blockIdx.y;
        const float* W = (z == 0) ? W0 : (z == 1) ? W1 : W2;
        {
            int kk = t >> 4, seg = t & 15;
            const float* s = W + (size_t)(kc * 16 + kk) * Dd + nt * 128 + seg * 8;
            float4 a = *(const float4*)s, b = *(const float4*)(s + 4);
            sm[kk][seg * 8 + 0] = a.x; sm[kk][seg * 8 + 1] = a.y;
            sm[kk][seg * 8 + 2] = a.z; sm[kk][seg * 8 + 3] = a.w;
            sm[kk][seg * 8 + 4] = b.x; sm[kk][seg * 8 + 5] = b.y;
            sm[kk][seg * 8 + 6] = b.z; sm[kk][seg * 8 + 7] = b.w;
        }
        __syncthreads();
        const int n = t >> 1, g = t & 1;
        char* bh = (char*)t_Whi + ((size_t)(z * 8 + nt) * 64 + kc) * 4096;
        char* bl = (char*)t_Wlo + ((size_t)(z * 8 + nt) * 64 + kc) * 4096;
#pragma unroll
        for (int j = 0; j < 4; j++) {
            int c2 = g * 4 + j;
            uint32_t hi, lo;
            split2(sm[2 * c2][n], sm[2 * c2 + 1][n], hi, lo);
            *(uint32_t*)(bh + swz(n, c2)) = hi;
            *(uint32_t*)(bl + swz(n, c2)) = lo;
        }
    }
}

// ---------------------------------------------------------------------------
// GEMM kernels (occupancy 2)
__global__ __launch_bounds__(256, 2) void qkv_mma() {
    const int nt = blockIdx.x, rt = blockIdx.y, z = blockIdx.z;
    float acc[4][4][4] = {};
    const size_t astride = (size_t)64 * 2048;
    gemm_run(t_Ehi + (size_t)rt * astride, t_Elo + (size_t)rt * astride,
             t_Whi + (size_t)(z * 8 + nt) * astride, t_Wlo + (size_t)(z * 8 + nt) * astride,
             32, acc);

    __half* Hi = (z == 0) ? t_Qhi : (z == 1) ? t_Khi : t_Vhi;
    __half* Lo = (z == 0) ? t_Qlo : (z == 1) ? t_Klo : t_Vlo;
    const int tid = threadIdx.x, lane = tid & 31, wid = tid >> 5;
    const int wr = wid >> 2, wc = wid & 3;
#pragma unroll
    for (int mi = 0; mi < 4; mi++)
#pragma unroll
        for (int ni = 0; ni < 4; ni++)
#pragma unroll
            for (int h = 0; h < 2; h++) {
                uint32_t hi, lo;
                split2(acc[mi][ni][h * 2], acc[mi][ni][h * 2 + 1], hi, lo);
                int R = wr * 64 + mi * 16 + (lane >> 2) + h * 8;
                int chunk = nt * 8 + wc * 2 + (ni >> 1);
                int c2 = (ni & 1) * 4 + (lane & 3);
                size_t blk = ((size_t)rt * 64 + chunk) * 4096;
                *(uint32_t*)((char*)Hi + blk + swz(R, c2)) = hi;
                *(uint32_t*)((char*)Lo + blk + swz(R, c2)) = lo;
            }
}

__global__ __launch_bounds__(256, 2) void scores_mma() {
    const int kt = blockIdx.x, qt = blockIdx.y, b = blockIdx.z;
    if (kt > qt) return;
    float acc[4][4][4] = {};
    const size_t astride = (size_t)64 * 2048;
    gemm_run(t_Qhi + (size_t)(b * 16 + qt) * astride, t_Qlo + (size_t)(b * 16 + qt) * astride,
             t_Khi + (size_t)(b * 16 + kt) * astride, t_Klo + (size_t)(b * 16 + kt) * astride,
             32, acc);

    float* out = g_S + (size_t)b * Ss * Ss;
    const int tid = threadIdx.x, lane = tid & 31, wid = tid >> 5;
    const int wr = wid >> 2, wc = wid & 3;
#pragma unroll
    for (int mi = 0; mi < 4; mi++)
#pragma unroll
        for (int ni = 0; ni < 4; ni++)
#pragma unroll
            for (int h = 0; h < 2; h++) {
                int R = qt * 128 + wr * 64 + mi * 16 + (lane >> 2) + h * 8;
                int C = kt * 128 + wc * 32 + ni * 8 + (lane & 3) * 2;
                float2 v = make_float2(acc[mi][ni][h * 2] * 0.03125f,
                                       acc[mi][ni][h * 2 + 1] * 0.03125f);
                *(float2*)(out + (size_t)R * Ss + C) = v;
            }
}

// ---------------------------------------------------------------------------
// Fused softmax + V-transpose. Independent workloads, merged into one grid:
//   blockIdx.x <  2048 : softmax of row q=blockIdx.x, batch b=blockIdx.y
//   blockIdx.x >= 2048 : transpose unit u=blockIdx.x-2048 (dt=u>>7, sc=u&127)
// Shared scratch: 8704B raw block; softmax view = 2048 floats (8192B),
// transpose view = 2 x [16][136] halves (8704B).
__global__ __launch_bounds__(256) void softmax_transpose() {
    __shared__ __align__(16) char sraw[8704];
    __shared__ float red[8];
    const int b = blockIdx.y, tid = threadIdx.x;

    if (blockIdx.x >= Ss) {
        // ---- V transpose unit (identical math to the old transpose_v) ----
        const int u = blockIdx.x - Ss;
        const int dt = u >> 7, sc = u & 127;
        __half* th = (__half*)sraw;              // [16][136]
        __half* tl = th + 16 * 136;
        const int srt = sc >> 3, srow0 = (sc & 7) * 16;
#pragma unroll
        for (int i = 0; i < 4; i++) {
            int idx = i * 256 + tid;
            int dc = idx >> 7, rr = (idx >> 3) & 15, c2 = idx & 7;
            const char* vh = (const char*)t_Vhi + ((size_t)(b * 16 + srt) * 64 + dt * 8 + dc) * 4096;
            const char* vl = (const char*)t_Vlo + ((size_t)(b * 16 + srt) * 64 + dt * 8 + dc) * 4096;
            uint32_t uh = *(const uint32_t*)(vh + swz(srow0 + rr, c2));
            uint32_t ul = *(const uint32_t*)(vl + swz(srow0 + rr, c2));
            __half2 hh = *(__half2*)&uh, hl = *(__half2*)&ul;
            int d = dc * 16 + c2 * 2;
            th[rr * 136 + d] = __low2half(hh); th[rr * 136 + d + 1] = __high2half(hh);
            tl[rr * 136 + d] = __low2half(hl); tl[rr * 136 + d + 1] = __high2half(hl);
        }
        __syncthreads();
        char* oh = (char*)t_VThi + ((size_t)(b * 8 + dt) * 128 + sc) * 4096;
        char* ol = (char*)t_VTlo + ((size_t)(b * 8 + dt) * 128 + sc) * 4096;
#pragma unroll
        for (int i = 0; i < 4; i++) {
            int idx = i * 256 + tid;
            int d = idx >> 3, c2 = idx & 7;
            *(uint32_t*)(oh + swz(d, c2)) = packh(th[(2 * c2) * 136 + d], th[(2 * c2 + 1) * 136 + d]);
            *(uint32_t*)(ol + swz(d, c2)) = packh(tl[(2 * c2) * 136 + d], tl[(2 * c2 + 1) * 136 + d]);
        }
        return;
    }

    // ---- softmax row ----
    float* sbuf = (float*)sraw;                  // 2048 floats = 8192B < 8704B
    const int q = blockIdx.x;
    const float* row = g_S + ((size_t)b * Ss + q) * Ss;
    const int len = q + 1;

    float m = -3.4e38f;
    for (int k = tid; k < len; k += 256) {
        float v = row[k];
        sbuf[k] = v;
        m = fmaxf(m, v);
    }
#pragma unroll
    for (int o = 16; o; o >>= 1) m = fmaxf(m, __shfl_xor_sync(0xffffffffu, m, o));
    if ((tid & 31) == 0) red[tid >> 5] = m;
    __syncthreads();
    float mall = red[0];
#pragma unroll
    for (int i = 1; i < 8; i++) mall = fmaxf(mall, red[i]);
    __syncthreads();

    float s = 0.f;
    for (int k = tid; k < len; k += 256) {
        float e = __expf(sbuf[k] - mall);
        sbuf[k] = e;
        s += e;
    }
#pragma unroll
    for (int o = 16; o; o >>= 1) s += __shfl_xor_sync(0xffffffffu, s, o);
    if ((tid & 31) == 0) red[tid >> 5] = s;
    __syncthreads();
    float sall = 0.f;
#pragma unroll
    for (int i = 0; i < 8; i++) sall += red[i];
    const float inv = 1.0f / sall;
    // (the sync above also makes all sbuf exp writes visible)

    const int fe = ((q >> 7) + 1) << 7;       // zero-fill through the PV k-tile
    char* Ph = (char*)t_Phi + ((size_t)(b * 16 + (q >> 7)) * 128) * 4096;
    char* Pl = (char*)t_Plo + ((size_t)(b * 16 + (q >> 7)) * 128) * 4096;
    const int qr = q & 127;
    for (int k = 2 * tid; k < fe; k += 512) {
        float p0 = (k     < len) ? sbuf[k] * inv : 0.f;
        float p1 = (k + 1 < len) ? sbuf[k + 1] * inv : 0.f;
        uint32_t hi, lo;
        split2(p0, p1, hi, lo);
        size_t blk = (size_t)(k >> 4) * 4096;
        int c2 = (k & 15) >> 1;
        *(uint32_t*)(Ph + blk + swz(qr, c2)) = hi;
        *(uint32_t*)(Pl + blk + swz(qr, c2)) = lo;
    }
}

// Longest q-tiles scheduled first: qt = 15 - blockIdx.x.
__global__ __launch_bounds__(256, 2) void pv_mma(float* __restrict__ O) {
    const int qt = 15 - blockIdx.x, dt = blockIdx.y, b = blockIdx.z;
    float acc[4][4][4] = {};
    const size_t pstride = (size_t)128 * 2048;
    gemm_run(t_Phi + (size_t)(b * 16 + qt) * pstride, t_Plo + (size_t)(b * 16 + qt) * pstride,
             t_VThi + (size_t)(b * 8 + dt) * pstride, t_VTlo + (size_t)(b * 8 + dt) * pstride,
             (qt + 1) * 4, acc);

    float* out = O + (size_t)b * Ss * Dd;
    const int tid = threadIdx.x, lane = tid & 31, wid = tid >> 5;
    const int wr = wid >> 2, wc = wid & 3;
#pragma unroll
    for (int mi = 0; mi < 4; mi++)
#pragma unroll
        for (int ni = 0; ni < 4; ni++)
#pragma unroll
            for (int h = 0; h < 2; h++) {
                int R = qt * 128 + wr * 64 + mi * 16 + (lane >> 2) + h * 8;
                int C = dt * 128 + wc * 32 + ni * 8 + (lane & 3) * 2;
                float2 v = make_float2(acc[mi][ni][h * 2], acc[mi][ni][h * 2 + 1]);
                *(float2*)(out + (size_t)R * Dd + C) = v;
            }
}

// ---------------------------------------------------------------------------
extern "C" void kernel_launch(void* const* d_in, const int* in_sizes, int n_in,
                              void* d_out, int out_size) {
    const float* E  = (const float*)d_in[0];
    const float* WQ = (const float*)d_in[1];
    const float* WK = (const float*)d_in[2];
    const float* WV = (const float*)d_in[3];
    float* O = (float*)d_out;

    // 96KB dynamic smem opt-in (legal under capture; executes immediately).
    cudaFuncSetAttribute(qkv_mma,    cudaFuncAttributeMaxDynamicSharedMemorySize, SMEM_TOTAL);
    cudaFuncSetAttribute(scores_mma, cudaFuncAttributeMaxDynamicSharedMemorySize, SMEM_TOTAL);
    cudaFuncSetAttribute(pv_mma,     cudaFuncAttributeMaxDynamicSharedMemorySize, SMEM_TOTAL);

    convert_ew<<<dim3(88, 64), 256>>>(E, WQ, WK, WV);
    qkv_mma<<<dim3(8, 64, 3), 256, SMEM_TOTAL>>>();
    scores_mma<<<dim3(16, 16, 4), 256, SMEM_TOTAL>>>();
    softmax_transpose<<<dim3(Ss + 1024, 4), 256>>>();
    pv_mma<<<dim3(16, 8, 4), 256, SMEM_TOTAL>>>(O);
}